// round 14
// baseline (speedup 1.0000x reference)
#include <cuda_runtime.h>
#include <cuda_fp16.h>
#include <cstdint>

#define B_   8
#define N_   2048
#define K_   32
#define D_   64
#define C1_  64
#define C2_  128
#define BN_  (B_*N_)
#define R2_  0.0225f
#define EPS_ 1e-5f
#define RCNT_ (1.0/524288.0)   /* exact: 2^-19 */

typedef unsigned long long ull;

// ---------------- helpers ----------------
__device__ __forceinline__ uint32_t smem_u32(const void* p) {
    uint32_t a;
    asm("{ .reg .u64 t; cvta.to.shared.u64 t, %1; cvt.u32.u64 %0, t; }" : "=r"(a) : "l"(p));
    return a;
}
#define SW128(off) ((off) ^ (((off) >> 3) & 0x70))

__device__ __forceinline__ void mma_f16(float* d, const uint32_t* a, const uint32_t* b) {
    asm volatile(
        "mma.sync.aligned.m16n8k16.row.col.f32.f16.f16.f32 "
        "{%0,%1,%2,%3}, {%4,%5,%6,%7}, {%8,%9}, {%0,%1,%2,%3};"
        : "+f"(d[0]), "+f"(d[1]), "+f"(d[2]), "+f"(d[3])
        : "r"(a[0]), "r"(a[1]), "r"(a[2]), "r"(a[3]), "r"(b[0]), "r"(b[1]));
}
__device__ __forceinline__ void ldsm_x4(uint32_t* r, uint32_t addr) {
    asm volatile("ldmatrix.sync.aligned.m8n8.x4.shared.b16 {%0,%1,%2,%3}, [%4];"
        : "=r"(r[0]), "=r"(r[1]), "=r"(r[2]), "=r"(r[3]) : "r"(addr));
}

// packed fp32x2 helpers (k_f1)
__device__ __forceinline__ void fma2(ull& d, ull a, ull b) {
    asm("fma.rn.f32x2 %0, %1, %2, %0;" : "+l"(d) : "l"(a), "l"(b));
}
__device__ __forceinline__ ull pack2(float x, float y) {
    ull r; asm("mov.b64 %0, {%1, %2};" : "=l"(r) : "f"(x), "f"(y)); return r;
}
__device__ __forceinline__ void unpack2(float& x, float& y, ull v) {
    asm("mov.b64 {%0, %1}, %2;" : "=f"(x), "=f"(y) : "l"(v));
}

// ---------------- device scratch ----------------
__device__ int    g_idx[BN_*K_];
__device__ float  g_F1[BN_*C1_];
__device__ double g_sum1[C1_], g_sq1[C1_];
__device__ double g_sum2[C2_], g_sq2[C2_];
__device__ float  g_x[BN_*C2_];     // per-(point,ch): max if gamma2>=0 else min
__device__ __half g_W2t[C2_*D_];    // [n][k] transposed W2, fp16

// ---------------- 1) F1 = feature @ W1[3:,:]  (+ folded init work) ----------------
__global__ void k_f1(const float* __restrict__ feat, const float* __restrict__ W1,
                     const float* __restrict__ W2) {
    __shared__ float sW[D_][C1_];
    __shared__ float sIn[32][D_+1];
    int t = threadIdx.x;
    if (blockIdx.x == 0) {
        if (t < C1_) { g_sum1[t] = 0.0; g_sq1[t] = 0.0; }
        if (t < C2_) { g_sum2[t] = 0.0; g_sq2[t] = 0.0; }
    }
    if (blockIdx.x < 32) {
        int i = blockIdx.x * 256 + t;
        int k = i >> 7, n = i & 127;
        g_W2t[n*D_ + k] = __float2half_rn(W2[i]);
    }

    int row0 = blockIdx.x * 32;
    for (int i = t; i < D_*C1_; i += 256)
        sW[i / C1_][i % C1_] = W1[(3 + i / C1_) * C1_ + (i % C1_)];
    for (int i = t; i < 32*D_; i += 256)
        sIn[i / D_][i % D_] = feat[(size_t)(row0 + i / D_) * D_ + (i % D_)];
    __syncthreads();
    int k = t >> 3, c0 = (t & 7) << 3;
    ull acc[4];
#pragma unroll
    for (int j = 0; j < 4; j++) acc[j] = 0ull;
    for (int i = 0; i < D_; i++) {
        ull a = pack2(sIn[k][i], sIn[k][i]);
        const ull* wr = (const ull*)&sW[i][c0];
#pragma unroll
        for (int j = 0; j < 4; j++) fma2(acc[j], a, wr[j]);
    }
    float* o = &g_F1[(size_t)(row0 + k) * C1_ + c0];
#pragma unroll
    for (int j = 0; j < 4; j++) { float x, y; unpack2(x, y, acc[j]); o[2*j] = x; o[2*j+1] = y; }
}

// ---------------- 2) fused ball query + h1 stats: float4-packed positions ----------------
__global__ void k_ballstats(const float* __restrict__ pos, const float* __restrict__ W1) {
    __shared__ float4 sp[N_];              // (x, y, z, |p|^2)  32 KB
    __shared__ int    sbuf[8][2][K_];
    __shared__ float  ssum[C1_], ssq[C1_];
    int t = threadIdx.x;
    int b    = blockIdx.x >> 7;
    int qblk = blockIdx.x & 127;
    const float* p = pos + (size_t)b * N_ * 3;
    for (int i = t; i < N_; i += 256) {
        float x = p[3*i], y = p[3*i+1], z = p[3*i+2];
        sp[i] = make_float4(x, y, z, x*x + y*y + z*z);
    }
    if (t < C1_) { ssum[t] = 0.f; ssq[t] = 0.f; }
    __syncthreads();

    int w = t >> 5, lane = t & 31;
    int qbase = qblk * 16 + w * 2;
    float4 qp0 = sp[qbase+0];
    float4 qp1 = sp[qbase+1];
    float qx0 = qp0.x, qy0 = qp0.y, qz0 = qp0.z, qn0 = qp0.w;
    float qx1 = qp1.x, qy1 = qp1.y, qz1 = qp1.z, qn1 = qp1.w;
    int cnt0 = 0, cnt1 = 0;

    for (int base = 0; base < N_; base += 32) {
        if (cnt0 >= K_ && cnt1 >= K_) break;
        int m = base + lane;
        float4 cp = sp[m];
        float cx = cp.x, cy = cp.y, cz = cp.z, cn = cp.w;
#define BALLQ(ii) \
        if (cnt##ii < K_) { \
            float dot = qx##ii*cx + qy##ii*cy + qz##ii*cz; \
            float sq  = qn##ii + cn - 2.0f*dot; \
            bool in   = (sq <= R2_); \
            unsigned msk = __ballot_sync(0xffffffffu, in); \
            if (in) { \
                int ps = cnt##ii + __popc(msk & ((1u << lane) - 1u)); \
                if (ps < K_) sbuf[w][ii][ps] = m; \
            } \
            cnt##ii += __popc(msk); \
        }
        BALLQ(0) BALLQ(1)
#undef BALLQ
    }
    __syncwarp();

    float wx0 = W1[2*lane],       wx1 = W1[2*lane+1];
    float wy0 = W1[C1_+2*lane],   wy1 = W1[C1_+2*lane+1];
    float wz0 = W1[2*C1_+2*lane], wz1 = W1[2*C1_+2*lane+1];
    const float* F1b = g_F1 + (size_t)b * N_ * C1_;

    float s0 = 0.f, s1 = 0.f, acq0 = 0.f, acq1 = 0.f;
    int cnts[2] = {cnt0, cnt1};
#pragma unroll
    for (int qq = 0; qq < 2; qq++) {
        int q = qbase + qq;
        int v = (lane < cnts[qq]) ? sbuf[w][qq][lane] : sbuf[w][qq][0];
        g_idx[(b*N_ + q)*K_ + lane] = v;
        float4 qp = sp[q];
        float qx = qp.x, qy = qp.y, qz = qp.z;
#pragma unroll 8
        for (int k = 0; k < K_; k++) {
            int m = __shfl_sync(0xffffffffu, v, k);
            float4 pm = sp[m];
            float dx = pm.x - qx, dy = pm.y - qy, dz = pm.z - qz;
            float2 f = *(const float2*)(F1b + (size_t)m * C1_ + 2*lane);
            float v0 = f.x + dx*wx0 + dy*wy0 + dz*wz0;
            float v1 = f.y + dx*wx1 + dy*wy1 + dz*wz1;
            s0 += v0; acq0 = fmaf(v0, v0, acq0);
            s1 += v1; acq1 = fmaf(v1, v1, acq1);
        }
    }
    atomicAdd(&ssum[2*lane],   s0);
    atomicAdd(&ssum[2*lane+1], s1);
    atomicAdd(&ssq [2*lane],   acq0);
    atomicAdd(&ssq [2*lane+1], acq1);
    __syncthreads();
    if (t < C1_) {
        atomicAdd(&g_sum1[t], (double)ssum[t]);
        atomicAdd(&g_sq1 [t], (double)ssq [t]);
    }
}

// ---------------- 3) HMMA gemm2: h-outer loop, S/Q accumulated across g ----------------
#define OFF_B    32768
#define OFF_EX   49152
#define G2T_SMEM (OFF_EX + 1728*4 + 1024)

extern __shared__ char dynraw[];
__global__ __launch_bounds__(256, 4)
void k_gemm2t(const float* __restrict__ pos, const float* __restrict__ W1,
              const float* __restrict__ gamma1, const float* __restrict__ beta1,
              const float* __restrict__ gamma2) {
    uint32_t rawb  = smem_u32(dynraw);
    uint32_t abase = (rawb + 1023) & ~1023u;
    char*    al    = dynraw + (abase - rawb);
    float*   ex    = (float*)(al + OFF_EX);

    float*  sWx   = ex;                    // 192
    float*  sA1   = ex + 192;              // 64
    float*  sB1   = ex + 256;              // 64
    float4* sMeta = (float4*)(ex + 320);   // 256 * float4 (dx,dy,dz,row)
    float*  ssum  = ex + 1344;             // 128
    float*  ssq   = ex + 1472;             // 128
    float*  sG2   = ex + 1600;             // 128

    int t   = threadIdx.x;
    int wid = t >> 5, lane = t & 31;
    int bn0 = blockIdx.x * 8;

    if (t < 3*C1_) sWx[t] = W1[t];
    if (t < C1_) {
        double mean = g_sum1[t] * RCNT_;
        double var  = g_sq1[t] * RCNT_ - mean * mean;
        float a = rsqrtf((float)var + EPS_) * gamma1[t];
        sA1[t] = a;
        sB1[t] = beta1[t] - (float)mean * a;
    }
    if (t < C2_)   { ssum[t] = 0.f; ssq[t] = 0.f; sG2[t] = gamma2[t]; }
    {
        int r  = t;
        int bn = bn0 + (r >> 5);
        int k  = r & 31;
        int b  = bn >> 11;
        int m  = g_idx[bn*K_ + k];
        float cx = pos[bn*3+0], cy = pos[bn*3+1], cz = pos[bn*3+2];
        const float* pm = pos + (size_t)(b*N_ + m) * 3;
        sMeta[r] = make_float4(pm[0]-cx, pm[1]-cy, pm[2]-cz,
                               __int_as_float(b*N_ + m));
    }

    // B tile: fp16, SW128
    for (int i = t; i < 128*16; i += 256) {
        int n = i >> 4, k8 = i & 15;
        uint32_t off = SW128((uint32_t)(n*128 + k8*8));
        *(ull*)(al + OFF_B + off) = ((const ull*)g_W2t)[i];
    }
    __syncthreads();

    // A tile build
    {
        int c = lane * 2;
        float w1x0 = sWx[c],        w1x1 = sWx[c+1];
        float w1y0 = sWx[C1_+c],    w1y1 = sWx[C1_+c+1];
        float w1z0 = sWx[2*C1_+c],  w1z1 = sWx[2*C1_+c+1];
        float a10  = sA1[c],        a11  = sA1[c+1];
        float b10  = sB1[c],        b11  = sB1[c+1];
#pragma unroll 4
        for (int j = 0; j < 32; j++) {
            int r = wid + j*8;
            float4 md = sMeta[r];
            float dx = md.x, dy = md.y, dz = md.z;
            int   m  = __float_as_int(md.w);
            float2 f = *(const float2*)(g_F1 + (size_t)m*C1_ + c);
            float v0 = f.x + dx*w1x0 + dy*w1y0 + dz*w1z0;
            float v1 = f.y + dx*w1x1 + dy*w1y1 + dz*w1z1;
            v0 = fmaxf(fmaf(v0, a10, b10), 0.f);
            v1 = fmaxf(fmaf(v1, a11, b11), 0.f);
            __half h0 = __float2half_rn(v0);
            __half h1 = __float2half_rn(v1);
            uint32_t hp = (uint32_t)*(const uint16_t*)&h0 | ((uint32_t)*(const uint16_t*)&h1 << 16);
            *(uint32_t*)(al + SW128((uint32_t)(r*128 + 4*lane))) = hp;
        }
    }
    __syncthreads();

    int w_r = wid & 3, w_c = wid >> 2;
    uint32_t Aa = abase, Bb = abase + OFF_B;

    int kbA = (lane >> 4) * 16;
    int kbB = ((lane >> 3) & 1) * 16;
    int rA  = w_r*32 + (lane & 15);
    int nBl = ((lane >> 4) << 3) + (lane & 7);

    // owned-column index (tree output ownership), per-h column
    int v0own = ((lane >> 2) & 1) * 4 + ((lane >> 3) & 1) * 2 + ((lane >> 4) & 1);
    int cbase = w_c*64 + (v0own >> 1) * 8 + 2*(lane & 3) + (v0own & 1);

#pragma unroll
    for (int h = 0; h < 2; h++) {
        int c0 = cbase + h*32;
        float g2sel = sG2[c0];
        float Sacc[8], Qacc[8];
#pragma unroll
        for (int tt = 0; tt < 8; tt++) { Sacc[tt] = 0.f; Qacc[tt] = 0.f; }

#pragma unroll
        for (int g = 0; g < 2; g++) {
            float acc[2][4][4];
#pragma unroll
            for (int mt = 0; mt < 2; mt++)
#pragma unroll
                for (int nt = 0; nt < 4; nt++)
#pragma unroll
                    for (int j = 0; j < 4; j++) acc[mt][nt][j] = 0.f;

#pragma unroll
            for (int ks = 0; ks < 4; ks++) {
                uint32_t ah[2][4], bb[2][4];
#pragma unroll
                for (int mt = 0; mt < 2; mt++)
                    ldsm_x4(ah[mt], Aa + SW128((uint32_t)((g*128 + rA + mt*16)*128 + ks*32 + kbA)));
#pragma unroll
                for (int np = 0; np < 2; np++)
                    ldsm_x4(bb[np], Bb + SW128((uint32_t)((w_c*64 + h*32 + np*16 + nBl)*128 + ks*32 + kbB)));
#pragma unroll
                for (int mt = 0; mt < 2; mt++)
#pragma unroll
                    for (int nt = 0; nt < 4; nt++)
                        mma_f16(acc[mt][nt], ah[mt], &bb[nt >> 1][(nt & 1) * 2]);
            }

            // in-thread reduce: MX/MN per g; S/Q accumulated across g
            float MX[8], MN[8];
#pragma unroll
            for (int nt = 0; nt < 4; nt++) {
                float a0 = acc[0][nt][0], a2 = acc[0][nt][2], b0 = acc[1][nt][0], b2 = acc[1][nt][2];
                MX[2*nt]   = fmaxf(fmaxf(a0, a2), fmaxf(b0, b2));
                MN[2*nt]   = fminf(fminf(a0, a2), fminf(b0, b2));
                Sacc[2*nt] += (a0 + a2) + (b0 + b2);
                Qacc[2*nt] += fmaf(a0,a0, fmaf(a2,a2, fmaf(b0,b0, b2*b2)));
                float a1 = acc[0][nt][1], a3 = acc[0][nt][3], b1 = acc[1][nt][1], b3 = acc[1][nt][3];
                MX[2*nt+1] = fmaxf(fmaxf(a1, a3), fmaxf(b1, b3));
                MN[2*nt+1] = fminf(fminf(a1, a3), fminf(b1, b3));
                Sacc[2*nt+1] += (a1 + a3) + (b1 + b3);
                Qacc[2*nt+1] += fmaf(a1,a1, fmaf(a3,a3, fmaf(b1,b1, b3*b3)));
            }
            // tree: MX/MN only
#pragma unroll
            for (int st = 0; st < 3; st++) {
                int d   = 4 << st;
                int len = 4 >> st;
                bool up = (lane & d) != 0;
#pragma unroll
                for (int tt = 0; tt < 4; tt++) {
                    if (tt >= len) break;
                    float sx_, rx, sn_, rn;
                    sx_ = up ? MX[tt] : MX[tt+len]; rx = __shfl_xor_sync(0xffffffffu, sx_, d);
                    MX[tt] = up ? fmaxf(MX[tt+len], rx) : fmaxf(MX[tt], rx);
                    sn_ = up ? MN[tt] : MN[tt+len]; rn = __shfl_xor_sync(0xffffffffu, sn_, d);
                    MN[tt] = up ? fminf(MN[tt+len], rn) : fminf(MN[tt], rn);
                }
            }
            int bnq = bn0 + g*4 + w_r;
            g_x[(size_t)bnq*C2_ + c0] = (g2sel >= 0.f) ? MX[0] : MN[0];
        }

        // tree: S/Q once per h (covers both g groups)
#pragma unroll
        for (int st = 0; st < 3; st++) {
            int d   = 4 << st;
            int len = 4 >> st;
            bool up = (lane & d) != 0;
#pragma unroll
            for (int tt = 0; tt < 4; tt++) {
                if (tt >= len) break;
                float ss_, rs, sq_, rq;
                ss_ = up ? Sacc[tt] : Sacc[tt+len]; rs = __shfl_xor_sync(0xffffffffu, ss_, d);
                Sacc[tt] = (up ? Sacc[tt+len] : Sacc[tt]) + rs;
                sq_ = up ? Qacc[tt] : Qacc[tt+len]; rq = __shfl_xor_sync(0xffffffffu, sq_, d);
                Qacc[tt] = (up ? Qacc[tt+len] : Qacc[tt]) + rq;
            }
        }
        atomicAdd(&ssum[c0], Sacc[0]);
        atomicAdd(&ssq [c0], Qacc[0]);
    }

    __syncthreads();
    if (t < C2_) {
        atomicAdd(&g_sum2[t], (double)ssum[t]);
        atomicAdd(&g_sq2 [t], (double)ssq [t]);
    }
}

// ---------------- 4) epilogue (BN2 inline; single buffer; fewer waves) ----------------
__global__ void k_out(const float* __restrict__ gamma2, const float* __restrict__ beta2,
                      const float* __restrict__ pos, float* __restrict__ out) {
    __shared__ float a2s[C2_], b2s[C2_];
    int t = threadIdx.x;
    if (t < C2_) {
        double mean = g_sum2[t] * RCNT_;
        double var  = g_sq2[t] * RCNT_ - mean * mean;
        float a = rsqrtf((float)var + EPS_) * gamma2[t];
        a2s[t] = a;
        b2s[t] = beta2[t] - (float)mean * a;
    }
    // pos passthrough: first 192 blocks copy 256 floats each (192*256 = 49152)
    if (blockIdx.x < 192) {
        int i = blockIdx.x * 256 + t;
        out[i] = pos[i];
    }
    __syncthreads();
    int t4 = t * 4;
    int c  = t4 & (C2_ - 1);
    float4 av = *(const float4*)&a2s[c];
    float4 bv = *(const float4*)&b2s[c];
    float* o2 = out + BN_*3;
    int base = blockIdx.x * 4096;
#pragma unroll
    for (int j = 0; j < 4; j++) {
        int e = base + j*1024 + t4;
        float4 xv = *(const float4*)&g_x[e];
        float4 r;
        r.x = fmaxf(fmaf(av.x, xv.x, bv.x), 0.f);
        r.y = fmaxf(fmaf(av.y, xv.y, bv.y), 0.f);
        r.z = fmaxf(fmaf(av.z, xv.z, bv.z), 0.f);
        r.w = fmaxf(fmaf(av.w, xv.w, bv.w), 0.f);
        *(float4*)&o2[e] = r;
    }
}

// ---------------- launch ----------------
extern "C" void kernel_launch(void* const* d_in, const int* in_sizes, int n_in,
                              void* d_out, int out_size) {
    const float* pos    = (const float*)d_in[0];
    const float* feat   = (const float*)d_in[1];
    const float* W1     = (const float*)d_in[2];
    const float* gamma1 = (const float*)d_in[3];
    const float* beta1  = (const float*)d_in[4];
    const float* W2     = (const float*)d_in[5];
    const float* gamma2 = (const float*)d_in[6];
    const float* beta2  = (const float*)d_in[7];
    float* out = (float*)d_out;

    cudaFuncSetAttribute(k_gemm2t, cudaFuncAttributeMaxDynamicSharedMemorySize, G2T_SMEM);

    k_f1        <<<BN_/32, 256>>>(feat, W1, W2);
    k_ballstats <<<B_*(N_/16), 256>>>(pos, W1);
    k_gemm2t    <<<BN_/8, 256, G2T_SMEM>>>(pos, W1, gamma1, beta1, gamma2);
    k_out       <<<BN_*C2_/4096, 256>>>(gamma2, beta2, pos, out);
}

// round 15
// speedup vs baseline: 1.1883x; 1.1883x over previous
#include <cuda_runtime.h>
#include <cuda_fp16.h>
#include <cstdint>

#define B_   8
#define N_   2048
#define K_   32
#define D_   64
#define C1_  64
#define C2_  128
#define BN_  (B_*N_)
#define R2_  0.0225f
#define EPS_ 1e-5f
#define RCNT_ (1.0/524288.0)   /* exact: 2^-19 */

typedef unsigned long long ull;

// ---------------- helpers ----------------
__device__ __forceinline__ uint32_t smem_u32(const void* p) {
    uint32_t a;
    asm("{ .reg .u64 t; cvta.to.shared.u64 t, %1; cvt.u32.u64 %0, t; }" : "=r"(a) : "l"(p));
    return a;
}
#define SW128(off) ((off) ^ (((off) >> 3) & 0x70))

__device__ __forceinline__ void mma_f16(float* d, const uint32_t* a, const uint32_t* b) {
    asm volatile(
        "mma.sync.aligned.m16n8k16.row.col.f32.f16.f16.f32 "
        "{%0,%1,%2,%3}, {%4,%5,%6,%7}, {%8,%9}, {%0,%1,%2,%3};"
        : "+f"(d[0]), "+f"(d[1]), "+f"(d[2]), "+f"(d[3])
        : "r"(a[0]), "r"(a[1]), "r"(a[2]), "r"(a[3]), "r"(b[0]), "r"(b[1]));
}
__device__ __forceinline__ void ldsm_x4(uint32_t* r, uint32_t addr) {
    asm volatile("ldmatrix.sync.aligned.m8n8.x4.shared.b16 {%0,%1,%2,%3}, [%4];"
        : "=r"(r[0]), "=r"(r[1]), "=r"(r[2]), "=r"(r[3]) : "r"(addr));
}

// packed fp32x2 helpers (k_f1)
__device__ __forceinline__ void fma2(ull& d, ull a, ull b) {
    asm("fma.rn.f32x2 %0, %1, %2, %0;" : "+l"(d) : "l"(a), "l"(b));
}
__device__ __forceinline__ ull pack2(float x, float y) {
    ull r; asm("mov.b64 %0, {%1, %2};" : "=l"(r) : "f"(x), "f"(y)); return r;
}
__device__ __forceinline__ void unpack2(float& x, float& y, ull v) {
    asm("mov.b64 {%0, %1}, %2;" : "=f"(x), "=f"(y) : "l"(v));
}

// ---------------- device scratch ----------------
__device__ int    g_idx[BN_*K_];
__device__ float  g_F1[BN_*C1_];
__device__ double g_sum1[C1_], g_sq1[C1_];
__device__ double g_sum2[C2_], g_sq2[C2_];
__device__ float  g_mx[BN_*C2_];
__device__ float  g_mn[BN_*C2_];
__device__ __half g_W2t[C2_*D_];   // [n][k] transposed W2, fp16

// ---------------- 1) F1 = feature @ W1[3:,:]  (+ folded init work) ----------------
__global__ void k_f1(const float* __restrict__ feat, const float* __restrict__ W1,
                     const float* __restrict__ W2) {
    __shared__ float sW[D_][C1_];
    __shared__ float sIn[32][D_+1];
    int t = threadIdx.x;
    if (blockIdx.x == 0) {
        if (t < C1_) { g_sum1[t] = 0.0; g_sq1[t] = 0.0; }
        if (t < C2_) { g_sum2[t] = 0.0; g_sq2[t] = 0.0; }
    }
    if (blockIdx.x < 32) {
        int i = blockIdx.x * 256 + t;
        int k = i >> 7, n = i & 127;
        g_W2t[n*D_ + k] = __float2half_rn(W2[i]);
    }

    int row0 = blockIdx.x * 32;
    for (int i = t; i < D_*C1_; i += 256)
        sW[i / C1_][i % C1_] = W1[(3 + i / C1_) * C1_ + (i % C1_)];
    for (int i = t; i < 32*D_; i += 256)
        sIn[i / D_][i % D_] = feat[(size_t)(row0 + i / D_) * D_ + (i % D_)];
    __syncthreads();
    int k = t >> 3, c0 = (t & 7) << 3;
    ull acc[4];
#pragma unroll
    for (int j = 0; j < 4; j++) acc[j] = 0ull;
    for (int i = 0; i < D_; i++) {
        ull a = pack2(sIn[k][i], sIn[k][i]);
        const ull* wr = (const ull*)&sW[i][c0];
#pragma unroll
        for (int j = 0; j < 4; j++) fma2(acc[j], a, wr[j]);
    }
    float* o = &g_F1[(size_t)(row0 + k) * C1_ + c0];
#pragma unroll
    for (int j = 0; j < 4; j++) { float x, y; unpack2(x, y, acc[j]); o[2*j] = x; o[2*j+1] = y; }
}

// ---------------- 2) fused ball query + h1 stats: float4-packed positions ----------------
__global__ void k_ballstats(const float* __restrict__ pos, const float* __restrict__ W1) {
    __shared__ float4 sp[N_];              // (x, y, z, |p|^2)  32 KB
    __shared__ int    sbuf[8][2][K_];
    __shared__ float  ssum[C1_], ssq[C1_];
    int t = threadIdx.x;
    int b    = blockIdx.x >> 7;
    int qblk = blockIdx.x & 127;
    const float* p = pos + (size_t)b * N_ * 3;
    for (int i = t; i < N_; i += 256) {
        float x = p[3*i], y = p[3*i+1], z = p[3*i+2];
        sp[i] = make_float4(x, y, z, x*x + y*y + z*z);
    }
    if (t < C1_) { ssum[t] = 0.f; ssq[t] = 0.f; }
    __syncthreads();

    int w = t >> 5, lane = t & 31;
    int qbase = qblk * 16 + w * 2;
    float4 qp0 = sp[qbase+0];
    float4 qp1 = sp[qbase+1];
    float qx0 = qp0.x, qy0 = qp0.y, qz0 = qp0.z, qn0 = qp0.w;
    float qx1 = qp1.x, qy1 = qp1.y, qz1 = qp1.z, qn1 = qp1.w;
    int cnt0 = 0, cnt1 = 0;

    for (int base = 0; base < N_; base += 32) {
        if (cnt0 >= K_ && cnt1 >= K_) break;
        int m = base + lane;
        float4 cp = sp[m];
        float cx = cp.x, cy = cp.y, cz = cp.z, cn = cp.w;
#define BALLQ(ii) \
        if (cnt##ii < K_) { \
            float dot = qx##ii*cx + qy##ii*cy + qz##ii*cz; \
            float sq  = qn##ii + cn - 2.0f*dot; \
            bool in   = (sq <= R2_); \
            unsigned msk = __ballot_sync(0xffffffffu, in); \
            if (in) { \
                int ps = cnt##ii + __popc(msk & ((1u << lane) - 1u)); \
                if (ps < K_) sbuf[w][ii][ps] = m; \
            } \
            cnt##ii += __popc(msk); \
        }
        BALLQ(0) BALLQ(1)
#undef BALLQ
    }
    __syncwarp();

    float wx0 = W1[2*lane],       wx1 = W1[2*lane+1];
    float wy0 = W1[C1_+2*lane],   wy1 = W1[C1_+2*lane+1];
    float wz0 = W1[2*C1_+2*lane], wz1 = W1[2*C1_+2*lane+1];
    const float* F1b = g_F1 + (size_t)b * N_ * C1_;

    float s0 = 0.f, s1 = 0.f, acq0 = 0.f, acq1 = 0.f;
    int cnts[2] = {cnt0, cnt1};
#pragma unroll
    for (int qq = 0; qq < 2; qq++) {
        int q = qbase + qq;
        int v = (lane < cnts[qq]) ? sbuf[w][qq][lane] : sbuf[w][qq][0];
        g_idx[(b*N_ + q)*K_ + lane] = v;
        float4 qp = sp[q];
        float qx = qp.x, qy = qp.y, qz = qp.z;
#pragma unroll 8
        for (int k = 0; k < K_; k++) {
            int m = __shfl_sync(0xffffffffu, v, k);
            float4 pm = sp[m];
            float dx = pm.x - qx, dy = pm.y - qy, dz = pm.z - qz;
            float2 f = *(const float2*)(F1b + (size_t)m * C1_ + 2*lane);
            float v0 = f.x + dx*wx0 + dy*wy0 + dz*wz0;
            float v1 = f.y + dx*wx1 + dy*wy1 + dz*wz1;
            s0 += v0; acq0 = fmaf(v0, v0, acq0);
            s1 += v1; acq1 = fmaf(v1, v1, acq1);
        }
    }
    atomicAdd(&ssum[2*lane],   s0);
    atomicAdd(&ssum[2*lane+1], s1);
    atomicAdd(&ssq [2*lane],   acq0);
    atomicAdd(&ssq [2*lane+1], acq1);
    __syncthreads();
    if (t < C1_) {
        atomicAdd(&g_sum1[t], (double)ssum[t]);
        atomicAdd(&g_sq1 [t], (double)ssq [t]);
    }
}

// ---------------- 3) HMMA gemm2: col-split tiles, 4 blocks/SM (round-12 proven) ----------------
#define OFF_B    32768
#define OFF_EX   49152
#define G2T_SMEM (OFF_EX + 1600*4 + 1024)

extern __shared__ char dynraw[];
__global__ __launch_bounds__(256, 4)
void k_gemm2t(const float* __restrict__ pos, const float* __restrict__ W1,
              const float* __restrict__ gamma1, const float* __restrict__ beta1) {
    uint32_t rawb  = smem_u32(dynraw);
    uint32_t abase = (rawb + 1023) & ~1023u;
    char*    al    = dynraw + (abase - rawb);
    float*   ex    = (float*)(al + OFF_EX);

    float*  sWx   = ex;                    // 192
    float*  sA1   = ex + 192;              // 64
    float*  sB1   = ex + 256;              // 64
    float4* sMeta = (float4*)(ex + 320);   // 256 * float4 (dx,dy,dz,row)
    float*  ssum  = ex + 1344;             // 128
    float*  ssq   = ex + 1472;             // 128  (ends at 1600)

    int t   = threadIdx.x;
    int wid = t >> 5, lane = t & 31;
    int bn0 = blockIdx.x * 8;

    if (t < 3*C1_) sWx[t] = W1[t];
    if (t < C1_) {
        double mean = g_sum1[t] * RCNT_;
        double var  = g_sq1[t] * RCNT_ - mean * mean;
        float a = rsqrtf((float)var + EPS_) * gamma1[t];
        sA1[t] = a;
        sB1[t] = beta1[t] - (float)mean * a;
    }
    if (t < C2_)   { ssum[t] = 0.f; ssq[t] = 0.f; }
    {
        int r  = t;
        int bn = bn0 + (r >> 5);
        int k  = r & 31;
        int b  = bn >> 11;
        int m  = g_idx[bn*K_ + k];
        float cx = pos[bn*3+0], cy = pos[bn*3+1], cz = pos[bn*3+2];
        const float* pm = pos + (size_t)(b*N_ + m) * 3;
        sMeta[r] = make_float4(pm[0]-cx, pm[1]-cy, pm[2]-cz,
                               __int_as_float(b*N_ + m));
    }

    // B tile: fp16, SW128
    for (int i = t; i < 128*16; i += 256) {
        int n = i >> 4, k8 = i & 15;
        uint32_t off = SW128((uint32_t)(n*128 + k8*8));
        *(ull*)(al + OFF_B + off) = ((const ull*)g_W2t)[i];
    }
    __syncthreads();

    // A tile build: fixed column-pair per thread; one LDS.128 metadata per row.
    {
        int c = lane * 2;
        float w1x0 = sWx[c],        w1x1 = sWx[c+1];
        float w1y0 = sWx[C1_+c],    w1y1 = sWx[C1_+c+1];
        float w1z0 = sWx[2*C1_+c],  w1z1 = sWx[2*C1_+c+1];
        float a10  = sA1[c],        a11  = sA1[c+1];
        float b10  = sB1[c],        b11  = sB1[c+1];
#pragma unroll 4
        for (int j = 0; j < 32; j++) {
            int r = wid + j*8;
            float4 md = sMeta[r];
            float dx = md.x, dy = md.y, dz = md.z;
            int   m  = __float_as_int(md.w);
            float2 f = *(const float2*)(g_F1 + (size_t)m*C1_ + c);
            float v0 = f.x + dx*w1x0 + dy*w1y0 + dz*w1z0;
            float v1 = f.y + dx*w1x1 + dy*w1y1 + dz*w1z1;
            v0 = fmaxf(fmaf(v0, a10, b10), 0.f);
            v1 = fmaxf(fmaf(v1, a11, b11), 0.f);
            __half h0 = __float2half_rn(v0);
            __half h1 = __float2half_rn(v1);
            uint32_t hp = (uint32_t)*(const uint16_t*)&h0 | ((uint32_t)*(const uint16_t*)&h1 << 16);
            *(uint32_t*)(al + SW128((uint32_t)(r*128 + 4*lane))) = hp;
        }
    }
    __syncthreads();

    // warp tiling: 4 row-warps x 2 col-warps; 64 cols as two sequential 32-col halves.
    int w_r = wid & 3, w_c = wid >> 2;
    uint32_t Aa = abase, Bb = abase + OFF_B;

    int kbA = (lane >> 4) * 16;
    int kbB = ((lane >> 3) & 1) * 16;
    int rA  = w_r*32 + (lane & 15);
    int nBl = ((lane >> 4) << 3) + (lane & 7);

#pragma unroll
    for (int g = 0; g < 2; g++) {
#pragma unroll
        for (int h = 0; h < 2; h++) {
            float acc[2][4][4];
#pragma unroll
            for (int mt = 0; mt < 2; mt++)
#pragma unroll
                for (int nt = 0; nt < 4; nt++)
#pragma unroll
                    for (int j = 0; j < 4; j++) acc[mt][nt][j] = 0.f;

#pragma unroll
            for (int ks = 0; ks < 4; ks++) {
                uint32_t ah[2][4], bb[2][4];
#pragma unroll
                for (int mt = 0; mt < 2; mt++)
                    ldsm_x4(ah[mt], Aa + SW128((uint32_t)((g*128 + rA + mt*16)*128 + ks*32 + kbA)));
#pragma unroll
                for (int np = 0; np < 2; np++)
                    ldsm_x4(bb[np], Bb + SW128((uint32_t)((w_c*64 + h*32 + np*16 + nBl)*128 + ks*32 + kbB)));
#pragma unroll
                for (int mt = 0; mt < 2; mt++)
#pragma unroll
                    for (int nt = 0; nt < 4; nt++)
                        mma_f16(acc[mt][nt], ah[mt], &bb[nt >> 1][(nt & 1) * 2]);
            }

            // ---- epilogue: in-thread reduce, split-ownership tree over 8 vars ----
            float MX[8], MN[8], S[8], Q[8];
#pragma unroll
            for (int nt = 0; nt < 4; nt++) {
                float a0 = acc[0][nt][0], a2 = acc[0][nt][2], b0 = acc[1][nt][0], b2 = acc[1][nt][2];
                MX[2*nt]   = fmaxf(fmaxf(a0, a2), fmaxf(b0, b2));
                MN[2*nt]   = fminf(fminf(a0, a2), fminf(b0, b2));
                S [2*nt]   = (a0 + a2) + (b0 + b2);
                Q [2*nt]   = fmaf(a0,a0, fmaf(a2,a2, fmaf(b0,b0, b2*b2)));
                float a1 = acc[0][nt][1], a3 = acc[0][nt][3], b1 = acc[1][nt][1], b3 = acc[1][nt][3];
                MX[2*nt+1] = fmaxf(fmaxf(a1, a3), fmaxf(b1, b3));
                MN[2*nt+1] = fminf(fminf(a1, a3), fminf(b1, b3));
                S [2*nt+1] = (a1 + a3) + (b1 + b3);
                Q [2*nt+1] = fmaf(a1,a1, fmaf(a3,a3, fmaf(b1,b1, b3*b3)));
            }
#pragma unroll
            for (int st = 0; st < 3; st++) {
                int d   = 4 << st;      // 4, 8, 16
                int len = 4 >> st;      // 4, 2, 1
                bool up = (lane & d) != 0;
#pragma unroll
                for (int tt = 0; tt < 4; tt++) {
                    if (tt >= len) break;
                    float sx_, rx, sn_, rn, ss_, rs, sq_, rq;
                    sx_ = up ? MX[tt] : MX[tt+len]; rx = __shfl_xor_sync(0xffffffffu, sx_, d);
                    MX[tt] = up ? fmaxf(MX[tt+len], rx) : fmaxf(MX[tt], rx);
                    sn_ = up ? MN[tt] : MN[tt+len]; rn = __shfl_xor_sync(0xffffffffu, sn_, d);
                    MN[tt] = up ? fminf(MN[tt+len], rn) : fminf(MN[tt], rn);
                    ss_ = up ? S[tt] : S[tt+len];   rs = __shfl_xor_sync(0xffffffffu, ss_, d);
                    S[tt]  = (up ? S[tt+len] : S[tt]) + rs;
                    sq_ = up ? Q[tt] : Q[tt+len];   rq = __shfl_xor_sync(0xffffffffu, sq_, d);
                    Q[tt]  = (up ? Q[tt+len] : Q[tt]) + rq;
                }
            }
            int v0 = ((lane >> 2) & 1) * 4 + ((lane >> 3) & 1) * 2 + ((lane >> 4) & 1);
            int c0 = w_c*64 + h*32 + (v0 >> 1) * 8 + 2*(lane & 3) + (v0 & 1);
            int bnq = bn0 + g*4 + w_r;
            g_mx[(size_t)bnq*C2_ + c0] = MX[0];
            g_mn[(size_t)bnq*C2_ + c0] = MN[0];
            atomicAdd(&ssum[c0], S[0]);
            atomicAdd(&ssq [c0], Q[0]);
        }
    }

    __syncthreads();
    if (t < C2_) {
        atomicAdd(&g_sum2[t], (double)ssum[t]);
        atomicAdd(&g_sq2 [t], (double)ssq [t]);
    }
}

// ---------------- 4) epilogue (BN2 inline; float4 I/O; pos passthrough folded) ----------------
__global__ void k_out(const float* __restrict__ gamma2, const float* __restrict__ beta2,
                      const float* __restrict__ pos, float* __restrict__ out) {
    __shared__ float a2s[C2_], b2s[C2_];
    int t = threadIdx.x;
    if (t < C2_) {
        double mean = g_sum2[t] * RCNT_;
        double var  = g_sq2[t] * RCNT_ - mean * mean;
        float a = rsqrtf((float)var + EPS_) * gamma2[t];
        a2s[t] = a;
        b2s[t] = beta2[t] - (float)mean * a;
    }
    // pos passthrough: first 192 blocks copy 256 floats each (192*256 = 49152)
    if (blockIdx.x < 192) {
        int i = blockIdx.x * 256 + t;
        out[i] = pos[i];
    }
    __syncthreads();
    int t4 = t * 4;
    int c  = t4 & (C2_ - 1);
    float4 av = *(const float4*)&a2s[c];
    float4 bv = *(const float4*)&b2s[c];
    float* o2 = out + BN_*3;
    int base = blockIdx.x * 2048;
#pragma unroll
    for (int j = 0; j < 2; j++) {
        int e = base + j*1024 + t4;
        float4 xm = *(const float4*)&g_mx[e];
        float4 xn = *(const float4*)&g_mn[e];
        float4 r;
        r.x = fmaxf(fmaf(av.x, (av.x >= 0.f) ? xm.x : xn.x, bv.x), 0.f);
        r.y = fmaxf(fmaf(av.y, (av.y >= 0.f) ? xm.y : xn.y, bv.y), 0.f);
        r.z = fmaxf(fmaf(av.z, (av.z >= 0.f) ? xm.z : xn.z, bv.z), 0.f);
        r.w = fmaxf(fmaf(av.w, (av.w >= 0.f) ? xm.w : xn.w, bv.w), 0.f);
        *(float4*)&o2[e] = r;
    }
}

// ---------------- launch ----------------
extern "C" void kernel_launch(void* const* d_in, const int* in_sizes, int n_in,
                              void* d_out, int out_size) {
    const float* pos    = (const float*)d_in[0];
    const float* feat   = (const float*)d_in[1];
    const float* W1     = (const float*)d_in[2];
    const float* gamma1 = (const float*)d_in[3];
    const float* beta1  = (const float*)d_in[4];
    const float* W2     = (const float*)d_in[5];
    const float* gamma2 = (const float*)d_in[6];
    const float* beta2  = (const float*)d_in[7];
    float* out = (float*)d_out;

    cudaFuncSetAttribute(k_gemm2t, cudaFuncAttributeMaxDynamicSharedMemorySize, G2T_SMEM);

    k_f1        <<<BN_/32, 256>>>(feat, W1, W2);
    k_ballstats <<<B_*(N_/16), 256>>>(pos, W1);
    k_gemm2t    <<<BN_/8, 256, G2T_SMEM>>>(pos, W1, gamma1, beta1);
    k_out       <<<BN_*C2_/2048, 256>>>(gamma2, beta2, pos, out);
}